// round 10
// baseline (speedup 1.0000x reference)
#include <cuda_runtime.h>
#include <cuda_bf16.h>

// LightGCN 3-layer. Padded-ELL (int2 slots {col*128, vbits}) built once,
// then 3x SpMM with FOUR ROWS PER WARP: 8-lane groups, each lane covers
// 8 dims (bf16x8 LDG.128 -> 2x sector efficiency vs LDG.64). Width-8
// immediate-source shfl broadcasts each group's own edge, so every
// instruction serves four edges. fp32 accumulate via packed fma.rn.f32x2.
// Slots >= cnt stay zero (module-load zero-init; g_cnt self-resets in
// MODE 2), so shorter rows' phantom edges contribute exactly 0.
// out = [emb0 (N*D fp32) | (emb0+y1+y2+y3)/4 fp32]

#define U_ROWS 100000
#define I_ROWS 50000
#define N_NODES (U_ROWS + I_ROWS)
#define EMB_D 64
#define TOTAL_F (N_NODES * EMB_D)
#define TOTAL_V4 (TOTAL_F / 4)
#define PAD 128
#define TPB 512
#define WARPS_PB (TPB / 32)

__device__ __nv_bfloat16 g_xA[TOTAL_F];
__device__ __nv_bfloat16 g_xB[TOTAL_F];
__device__ float         g_acc[TOTAL_F];
__device__ int2          g_slots[(size_t)N_NODES * PAD];  // {col*128, vbits}
__device__ int           g_cnt[N_NODES];                  // zero-init; self-reset

// ---------------------------------------------------------------------------
// fused init + build
// ---------------------------------------------------------------------------
__global__ __launch_bounds__(TPB) void init_build_kernel(
        const float4* __restrict__ u,
        const float4* __restrict__ it,
        float4* __restrict__ out,
        const int*   __restrict__ rows,
        const int*   __restrict__ cols,
        const float* __restrict__ vals,
        int nnz, int init_blocks) {
    if ((int)blockIdx.x < init_blocks) {
        int i = blockIdx.x * TPB + threadIdx.x;
        if (i >= TOTAL_V4) return;
        const int u_v4 = U_ROWS * EMB_D / 4;
        float4 v = (i < u_v4) ? u[i] : it[i - u_v4];
        ((float4*)g_acc)[i] = v;
        out[i] = v;
        __nv_bfloat162* xa = (__nv_bfloat162*)g_xA;
        xa[2 * i]     = __floats2bfloat162_rn(v.x, v.y);
        xa[2 * i + 1] = __floats2bfloat162_rn(v.z, v.w);
    } else {
        int e = (blockIdx.x - init_blocks) * TPB + threadIdx.x;
        if (e >= nnz) return;
        int r = rows[e];
        int pos = atomicAdd(&g_cnt[r], 1);
        if (pos < PAD)   // always true for this dataset (Poisson(32) degrees)
            g_slots[(size_t)r * PAD + pos] =
                make_int2(cols[e] * 128, __float_as_int(vals[e]));
    }
}

// ---------------------------------------------------------------------------
// per-edge op: gather bf16x8 (8 dims, LDG.128), unpack 4x, four f32x2 FMAs
// ---------------------------------------------------------------------------
__device__ __forceinline__ void edge_fma8(unsigned long long& a0,
                                          unsigned long long& a1,
                                          unsigned long long& a2,
                                          unsigned long long& a3,
                                          const char* __restrict__ xb,
                                          int coff, int vbits) {
    uint4 xr = *(const uint4*)(xb + coff);   // LDG.128: 8 bf16 dims
    asm("{\n\t"
        ".reg .b32 lo, hi;\n\t"
        ".reg .b64 xx, vv;\n\t"
        "mov.b64 vv, {%5, %5};\n\t"
        "shl.b32 lo, %4, 16;\n\t"
        "and.b32 hi, %4, 0xffff0000;\n\t"
        "mov.b64 xx, {lo, hi};\n\t"
        "fma.rn.f32x2 %0, vv, xx, %0;\n\t"
        "shl.b32 lo, %6, 16;\n\t"
        "and.b32 hi, %6, 0xffff0000;\n\t"
        "mov.b64 xx, {lo, hi};\n\t"
        "fma.rn.f32x2 %1, vv, xx, %1;\n\t"
        "shl.b32 lo, %7, 16;\n\t"
        "and.b32 hi, %7, 0xffff0000;\n\t"
        "mov.b64 xx, {lo, hi};\n\t"
        "fma.rn.f32x2 %2, vv, xx, %2;\n\t"
        "shl.b32 lo, %8, 16;\n\t"
        "and.b32 hi, %8, 0xffff0000;\n\t"
        "mov.b64 xx, {lo, hi};\n\t"
        "fma.rn.f32x2 %3, vv, xx, %3;\n\t"
        "}"
        : "+l"(a0), "+l"(a1), "+l"(a2), "+l"(a3)
        : "r"(xr.x), "r"(vbits), "r"(xr.y), "r"(xr.z), "r"(xr.w));
}

// ---------------------------------------------------------------------------
// spmm<MODE>: four rows per warp (one per 8-lane group), 8 dims per lane.
//   MODE 0: x=g_xA, y(bf16)->g_xB, acc += y
//   MODE 1: x=g_xB, y(bf16)->g_xA, acc += y
//   MODE 2: x=g_xA, out2[r] = (acc[r] + y) * 0.25 ; reset g_cnt[r]
// ---------------------------------------------------------------------------
template <int MODE>
__global__ __launch_bounds__(TPB, 3) void spmm_ell_kernel(
        float4* __restrict__ out2) {
    int gw    = (blockIdx.x * blockDim.x + threadIdx.x) >> 5;  // warp id
    int lane  = threadIdx.x & 31;
    int group = lane >> 3;          // 0..3 : which row of the warp
    int sub   = lane & 7;           // dim group: dims [sub*8, sub*8+8)
    int row   = gw * 4 + group;
    if (row >= N_NODES) return;     // N_NODES % 4 == 0: whole warp exits

    const char* __restrict__ xb =
        (const char*)((MODE == 1) ? g_xB : g_xA) + sub * 16;

    int cnt = min(g_cnt[row], PAD);
    int mcnt = max(cnt, __shfl_xor_sync(0xffffffffu, cnt, 8));
    mcnt = max(mcnt, __shfl_xor_sync(0xffffffffu, mcnt, 16));
    const int2* __restrict__ sl = g_slots + (size_t)row * PAD;

    unsigned long long a0 = 0ull;   // f32 pair: dims 8sub+0, 8sub+1
    unsigned long long a1 = 0ull;   // dims 8sub+2, 8sub+3
    unsigned long long a2 = 0ull;   // dims 8sub+4, 8sub+5
    unsigned long long a3 = 0ull;   // dims 8sub+6, 8sub+7

    // prefetch first chunk; slots >= cnt are zero -> phantom edges are no-ops
    int2 s = sl[sub];
    for (int base = 0; base < mcnt; base += 8) {
        int nb = base + 8;
        int2 snext = (nb < mcnt) ? sl[nb + sub] : make_int2(0, 0);
        #pragma unroll
        for (int k = 0; k < 8; k++) {
            int coff = __shfl_sync(0xffffffffu, s.x, k, 8);
            int vb   = __shfl_sync(0xffffffffu, s.y, k, 8);
            edge_fma8(a0, a1, a2, a3, xb, coff, vb);
        }
        s = snext;
    }

    float f0 = __uint_as_float((unsigned)a0);
    float f1 = __uint_as_float((unsigned)(a0 >> 32));
    float f2 = __uint_as_float((unsigned)a1);
    float f3 = __uint_as_float((unsigned)(a1 >> 32));
    float f4 = __uint_as_float((unsigned)a2);
    float f5 = __uint_as_float((unsigned)(a2 >> 32));
    float f6 = __uint_as_float((unsigned)a3);
    float f7 = __uint_as_float((unsigned)(a3 >> 32));

    int o4 = row * 16 + sub * 2;    // float4 index: lane owns o4 and o4+1
    if (MODE == 2) {
        float4 p = ((const float4*)g_acc)[o4];
        float4 q = ((const float4*)g_acc)[o4 + 1];
        out2[o4]     = make_float4((p.x + f0) * 0.25f, (p.y + f1) * 0.25f,
                                   (p.z + f2) * 0.25f, (p.w + f3) * 0.25f);
        out2[o4 + 1] = make_float4((q.x + f4) * 0.25f, (q.y + f5) * 0.25f,
                                   (q.z + f6) * 0.25f, (q.w + f7) * 0.25f);
        if (sub == 0) g_cnt[row] = 0;   // restore invariant for next call
    } else {
        __nv_bfloat162* xn = (__nv_bfloat162*)((MODE == 0) ? g_xB : g_xA);
        int ob = row * 32 + sub * 4;    // bf16x2 index
        xn[ob]     = __floats2bfloat162_rn(f0, f1);
        xn[ob + 1] = __floats2bfloat162_rn(f2, f3);
        xn[ob + 2] = __floats2bfloat162_rn(f4, f5);
        xn[ob + 3] = __floats2bfloat162_rn(f6, f7);
        float4 p = ((float4*)g_acc)[o4];
        float4 q = ((float4*)g_acc)[o4 + 1];
        ((float4*)g_acc)[o4]     = make_float4(p.x + f0, p.y + f1,
                                               p.z + f2, p.w + f3);
        ((float4*)g_acc)[o4 + 1] = make_float4(q.x + f4, q.y + f5,
                                               q.z + f6, q.w + f7);
    }
}

extern "C" void kernel_launch(void* const* d_in, const int* in_sizes, int n_in,
                              void* d_out, int out_size) {
    const float* user_emb = (const float*)d_in[0];
    const float* item_emb = (const float*)d_in[1];
    const float* edge_val = (const float*)d_in[2];
    const int*   edge_row = (const int*)d_in[3];
    const int*   edge_col = (const int*)d_in[4];
    const int nnz = in_sizes[2];

    float* out  = (float*)d_out;
    float* out2 = out + TOTAL_F;

    const int init_blocks  = (TOTAL_V4 + TPB - 1) / TPB;
    const int build_blocks = (nnz + TPB - 1) / TPB;
    const int rows_per_blk = WARPS_PB * 4;
    const int spmm_blocks  = (N_NODES + rows_per_blk - 1) / rows_per_blk;

    init_build_kernel<<<init_blocks + build_blocks, TPB>>>(
        (const float4*)user_emb, (const float4*)item_emb, (float4*)out,
        edge_row, edge_col, edge_val, nnz, init_blocks);

    spmm_ell_kernel<0><<<spmm_blocks, TPB>>>(nullptr);        // xA -> xB, acc+=
    spmm_ell_kernel<1><<<spmm_blocks, TPB>>>(nullptr);        // xB -> xA, acc+=
    spmm_ell_kernel<2><<<spmm_blocks, TPB>>>((float4*)out2);  // out2=(acc+y)/4
}

// round 11
// speedup vs baseline: 1.0047x; 1.0047x over previous
#include <cuda_runtime.h>
#include <cuda_bf16.h>

// LightGCN 3-layer. Padded-ELL (int2 slots {col*128, vbits}) built once,
// then 3x SpMM with TWO ROWS PER WARP (round-9 sweet spot: lanes 0-15 ->
// row 2w, 16-31 -> 2w+1; 4 dims/lane via bf16x4 LDG.64; width-16
// immediate-source shfl). Round 11: build vectorized 4 edges/thread
// (int4/float4 index loads) to cut build-phase load issues 4x.
// No atomics in the SpMM hot path; g_cnt self-resets in MODE 2.
// out = [emb0 (N*D fp32) | (emb0+y1+y2+y3)/4 fp32]

#define U_ROWS 100000
#define I_ROWS 50000
#define N_NODES (U_ROWS + I_ROWS)
#define EMB_D 64
#define TOTAL_F (N_NODES * EMB_D)
#define TOTAL_V4 (TOTAL_F / 4)
#define PAD 128
#define TPB 512
#define WARPS_PB (TPB / 32)

__device__ __nv_bfloat16 g_xA[TOTAL_F];
__device__ __nv_bfloat16 g_xB[TOTAL_F];
__device__ float         g_acc[TOTAL_F];
__device__ int2          g_slots[(size_t)N_NODES * PAD];  // {col*128, vbits}
__device__ int           g_cnt[N_NODES];                  // zero-init; self-reset

// ---------------------------------------------------------------------------
// build helper: one edge -> its row's next ELL slot
// ---------------------------------------------------------------------------
__device__ __forceinline__ void put_edge(int r, int c, float v) {
    int pos = atomicAdd(&g_cnt[r], 1);
    if (pos < PAD)   // always true for this dataset (Poisson(32) degrees)
        g_slots[(size_t)r * PAD + pos] = make_int2(c * 128, __float_as_int(v));
}

// ---------------------------------------------------------------------------
// fused init + build (build: 4 edges per thread, vectorized loads)
// ---------------------------------------------------------------------------
__global__ __launch_bounds__(TPB) void init_build_kernel(
        const float4* __restrict__ u,
        const float4* __restrict__ it,
        float4* __restrict__ out,
        const int*   __restrict__ rows,
        const int*   __restrict__ cols,
        const float* __restrict__ vals,
        int nnz, int init_blocks) {
    if ((int)blockIdx.x < init_blocks) {
        int i = blockIdx.x * TPB + threadIdx.x;
        if (i >= TOTAL_V4) return;
        const int u_v4 = U_ROWS * EMB_D / 4;
        float4 v = (i < u_v4) ? u[i] : it[i - u_v4];
        ((float4*)g_acc)[i] = v;
        out[i] = v;
        __nv_bfloat162* xa = (__nv_bfloat162*)g_xA;
        xa[2 * i]     = __floats2bfloat162_rn(v.x, v.y);
        xa[2 * i + 1] = __floats2bfloat162_rn(v.z, v.w);
    } else {
        int t = (blockIdx.x - init_blocks) * TPB + threadIdx.x;
        int e = t * 4;
        if (e + 3 < nnz) {
            int4   r4 = ((const int4*)rows)[t];
            int4   c4 = ((const int4*)cols)[t];
            float4 v4 = ((const float4*)vals)[t];
            put_edge(r4.x, c4.x, v4.x);
            put_edge(r4.y, c4.y, v4.y);
            put_edge(r4.z, c4.z, v4.z);
            put_edge(r4.w, c4.w, v4.w);
        } else {
            for (; e < nnz; e++) put_edge(rows[e], cols[e], vals[e]);
        }
    }
}

// ---------------------------------------------------------------------------
// per-edge op: gather bf16x4 (4 dims), unpack 2x, two packed f32x2 FMAs
// ---------------------------------------------------------------------------
__device__ __forceinline__ void edge_fma4(unsigned long long& accLo,
                                          unsigned long long& accHi,
                                          const char* __restrict__ xb,
                                          int coff, int vbits) {
    uint2 xr = *(const uint2*)(xb + coff);   // LDG.64: 4 bf16 dims
    asm("{\n\t"
        ".reg .b32 lo, hi;\n\t"
        ".reg .b64 xx, vv;\n\t"
        "mov.b64 vv, {%3, %3};\n\t"
        "shl.b32 lo, %2, 16;\n\t"
        "and.b32 hi, %2, 0xffff0000;\n\t"
        "mov.b64 xx, {lo, hi};\n\t"
        "fma.rn.f32x2 %0, vv, xx, %0;\n\t"
        "shl.b32 lo, %4, 16;\n\t"
        "and.b32 hi, %4, 0xffff0000;\n\t"
        "mov.b64 xx, {lo, hi};\n\t"
        "fma.rn.f32x2 %1, vv, xx, %1;\n\t"
        "}"
        : "+l"(accLo), "+l"(accHi)
        : "r"(xr.x), "r"(vbits), "r"(xr.y));
}

// ---------------------------------------------------------------------------
// spmm<MODE>: two rows per warp, 4 dims per lane (round-9 configuration).
//   MODE 0: x=g_xA, y(bf16)->g_xB, acc += y
//   MODE 1: x=g_xB, y(bf16)->g_xA, acc += y
//   MODE 2: x=g_xA, out2[r] = (acc[r] + y) * 0.25 ; reset g_cnt[r]
// ---------------------------------------------------------------------------
template <int MODE>
__global__ __launch_bounds__(TPB, 4) void spmm_ell_kernel(
        float4* __restrict__ out2) {
    int gw   = (blockIdx.x * blockDim.x + threadIdx.x) >> 5;
    int lane = threadIdx.x & 31;
    int half = lane >> 4;
    int sub  = lane & 15;
    int row  = gw * 2 + half;
    if (row >= N_NODES) return;

    const char* __restrict__ xb =
        (const char*)((MODE == 1) ? g_xB : g_xA) + sub * 8;

    int cnt = min(g_cnt[row], PAD);
    int mcnt = max(cnt, __shfl_xor_sync(0xffffffffu, cnt, 16));
    const int2* __restrict__ sl = g_slots + (size_t)row * PAD;

    unsigned long long accLo = 0ull;   // f32 pair: dims 4sub+0, 4sub+1
    unsigned long long accHi = 0ull;   // f32 pair: dims 4sub+2, 4sub+3

    // prefetch first chunk; slots >= cnt are zero -> phantom edges are no-ops
    int2 s = sl[sub];
    for (int base = 0; base < mcnt; base += 16) {
        int nb = base + 16;
        int2 snext = (nb < mcnt) ? sl[nb + sub] : make_int2(0, 0);
        #pragma unroll
        for (int k = 0; k < 16; k++) {
            int coff = __shfl_sync(0xffffffffu, s.x, k, 16);
            int vb   = __shfl_sync(0xffffffffu, s.y, k, 16);
            edge_fma4(accLo, accHi, xb, coff, vb);
        }
        s = snext;
    }

    float a0 = __uint_as_float((unsigned)accLo);
    float a1 = __uint_as_float((unsigned)(accLo >> 32));
    float a2 = __uint_as_float((unsigned)accHi);
    float a3 = __uint_as_float((unsigned)(accHi >> 32));

    int off = row * 16 + sub;   // float4 / bf16x4 granularity
    if (MODE == 2) {
        float4 a = ((const float4*)g_acc)[off];
        out2[off] = make_float4((a.x + a0) * 0.25f, (a.y + a1) * 0.25f,
                                (a.z + a2) * 0.25f, (a.w + a3) * 0.25f);
        if (sub == 0) g_cnt[row] = 0;   // restore invariant for next call
    } else {
        __nv_bfloat162* xn = (__nv_bfloat162*)((MODE == 0) ? g_xB : g_xA);
        xn[2 * off]     = __floats2bfloat162_rn(a0, a1);
        xn[2 * off + 1] = __floats2bfloat162_rn(a2, a3);
        float4 a = ((float4*)g_acc)[off];
        ((float4*)g_acc)[off] =
            make_float4(a.x + a0, a.y + a1, a.z + a2, a.w + a3);
    }
}

extern "C" void kernel_launch(void* const* d_in, const int* in_sizes, int n_in,
                              void* d_out, int out_size) {
    const float* user_emb = (const float*)d_in[0];
    const float* item_emb = (const float*)d_in[1];
    const float* edge_val = (const float*)d_in[2];
    const int*   edge_row = (const int*)d_in[3];
    const int*   edge_col = (const int*)d_in[4];
    const int nnz = in_sizes[2];

    float* out  = (float*)d_out;
    float* out2 = out + TOTAL_F;

    const int init_blocks  = (TOTAL_V4 + TPB - 1) / TPB;
    const int edge_threads = (nnz + 3) / 4;
    const int build_blocks = (edge_threads + TPB - 1) / TPB;
    const int rows_per_blk = WARPS_PB * 2;
    const int spmm_blocks  = (N_NODES + rows_per_blk - 1) / rows_per_blk;

    init_build_kernel<<<init_blocks + build_blocks, TPB>>>(
        (const float4*)user_emb, (const float4*)item_emb, (float4*)out,
        edge_row, edge_col, edge_val, nnz, init_blocks);

    spmm_ell_kernel<0><<<spmm_blocks, TPB>>>(nullptr);        // xA -> xB, acc+=
    spmm_ell_kernel<1><<<spmm_blocks, TPB>>>(nullptr);        // xB -> xA, acc+=
    spmm_ell_kernel<2><<<spmm_blocks, TPB>>>((float4*)out2);  // out2=(acc+y)/4
}

// round 12
// speedup vs baseline: 1.0626x; 1.0577x over previous
#include <cuda_runtime.h>
#include <cuda_bf16.h>

// LightGCN 3-layer. Padded-ELL (int2 slots {col*128, vbits}) built once,
// then 3x SpMM with TWO ROWS PER WARP (lanes 0-15 -> row 2w, 16-31 -> 2w+1;
// 4 dims/lane via bf16x4 LDG.64; width-16 immediate-source shfl).
// Round 12: remainder processed at 4-step granularity instead of rounding
// the row up to full 16-step chunks (Poisson(32) rows wasted ~33% of inner
// iterations on phantom zero-edges; now ~5%).
// No atomics in the SpMM hot path; g_cnt self-resets in MODE 2.
// out = [emb0 (N*D fp32) | (emb0+y1+y2+y3)/4 fp32]

#define U_ROWS 100000
#define I_ROWS 50000
#define N_NODES (U_ROWS + I_ROWS)
#define EMB_D 64
#define TOTAL_F (N_NODES * EMB_D)
#define TOTAL_V4 (TOTAL_F / 4)
#define PAD 128
#define TPB 512
#define WARPS_PB (TPB / 32)

__device__ __nv_bfloat16 g_xA[TOTAL_F];
__device__ __nv_bfloat16 g_xB[TOTAL_F];
__device__ float         g_acc[TOTAL_F];
__device__ int2          g_slots[(size_t)N_NODES * PAD];  // {col*128, vbits}
__device__ int           g_cnt[N_NODES];                  // zero-init; self-reset

// ---------------------------------------------------------------------------
// build helper: one edge -> its row's next ELL slot
// ---------------------------------------------------------------------------
__device__ __forceinline__ void put_edge(int r, int c, float v) {
    int pos = atomicAdd(&g_cnt[r], 1);
    if (pos < PAD)   // always true for this dataset (Poisson(32) degrees)
        g_slots[(size_t)r * PAD + pos] = make_int2(c * 128, __float_as_int(v));
}

// ---------------------------------------------------------------------------
// fused init + build (build: 4 edges per thread, vectorized loads)
// ---------------------------------------------------------------------------
__global__ __launch_bounds__(TPB) void init_build_kernel(
        const float4* __restrict__ u,
        const float4* __restrict__ it,
        float4* __restrict__ out,
        const int*   __restrict__ rows,
        const int*   __restrict__ cols,
        const float* __restrict__ vals,
        int nnz, int init_blocks) {
    if ((int)blockIdx.x < init_blocks) {
        int i = blockIdx.x * TPB + threadIdx.x;
        if (i >= TOTAL_V4) return;
        const int u_v4 = U_ROWS * EMB_D / 4;
        float4 v = (i < u_v4) ? u[i] : it[i - u_v4];
        ((float4*)g_acc)[i] = v;
        out[i] = v;
        __nv_bfloat162* xa = (__nv_bfloat162*)g_xA;
        xa[2 * i]     = __floats2bfloat162_rn(v.x, v.y);
        xa[2 * i + 1] = __floats2bfloat162_rn(v.z, v.w);
    } else {
        int t = (blockIdx.x - init_blocks) * TPB + threadIdx.x;
        int e = t * 4;
        if (e + 3 < nnz) {
            int4   r4 = ((const int4*)rows)[t];
            int4   c4 = ((const int4*)cols)[t];
            float4 v4 = ((const float4*)vals)[t];
            put_edge(r4.x, c4.x, v4.x);
            put_edge(r4.y, c4.y, v4.y);
            put_edge(r4.z, c4.z, v4.z);
            put_edge(r4.w, c4.w, v4.w);
        } else {
            for (; e < nnz; e++) put_edge(rows[e], cols[e], vals[e]);
        }
    }
}

// ---------------------------------------------------------------------------
// per-edge op: gather bf16x4 (4 dims), unpack 2x, two packed f32x2 FMAs
// ---------------------------------------------------------------------------
__device__ __forceinline__ void edge_fma4(unsigned long long& accLo,
                                          unsigned long long& accHi,
                                          const char* __restrict__ xb,
                                          int coff, int vbits) {
    uint2 xr = *(const uint2*)(xb + coff);   // LDG.64: 4 bf16 dims
    asm("{\n\t"
        ".reg .b32 lo, hi;\n\t"
        ".reg .b64 xx, vv;\n\t"
        "mov.b64 vv, {%3, %3};\n\t"
        "shl.b32 lo, %2, 16;\n\t"
        "and.b32 hi, %2, 0xffff0000;\n\t"
        "mov.b64 xx, {lo, hi};\n\t"
        "fma.rn.f32x2 %0, vv, xx, %0;\n\t"
        "shl.b32 lo, %4, 16;\n\t"
        "and.b32 hi, %4, 0xffff0000;\n\t"
        "mov.b64 xx, {lo, hi};\n\t"
        "fma.rn.f32x2 %1, vv, xx, %1;\n\t"
        "}"
        : "+l"(accLo), "+l"(accHi)
        : "r"(xr.x), "r"(vbits), "r"(xr.y));
}

// ---------------------------------------------------------------------------
// spmm<MODE>: two rows per warp, 4 dims per lane.
//   MODE 0: x=g_xA, y(bf16)->g_xB, acc += y
//   MODE 1: x=g_xB, y(bf16)->g_xA, acc += y
//   MODE 2: x=g_xA, out2[r] = (acc[r] + y) * 0.25 ; reset g_cnt[r]
// ---------------------------------------------------------------------------
template <int MODE>
__global__ __launch_bounds__(TPB, 4) void spmm_ell_kernel(
        float4* __restrict__ out2) {
    int gw   = (blockIdx.x * blockDim.x + threadIdx.x) >> 5;
    int lane = threadIdx.x & 31;
    int half = lane >> 4;
    int sub  = lane & 15;
    int row  = gw * 2 + half;
    if (row >= N_NODES) return;

    const char* __restrict__ xb =
        (const char*)((MODE == 1) ? g_xB : g_xA) + sub * 8;

    int cnt = min(g_cnt[row], PAD);
    int mcnt = max(cnt, __shfl_xor_sync(0xffffffffu, cnt, 16));
    const int2* __restrict__ sl = g_slots + (size_t)row * PAD;

    unsigned long long accLo = 0ull;   // f32 pair: dims 4sub+0, 4sub+1
    unsigned long long accHi = 0ull;   // f32 pair: dims 4sub+2, 4sub+3

    // main loop: full 16-step chunks with next-chunk prefetch
    int2 s = sl[sub];
    int base = 0;
    for (; base + 16 <= mcnt; base += 16) {
        int nb = base + 16;
        int2 snext = (nb < mcnt) ? sl[nb + sub] : make_int2(0, 0);
        #pragma unroll
        for (int k = 0; k < 16; k++) {
            int coff = __shfl_sync(0xffffffffu, s.x, k, 16);
            int vb   = __shfl_sync(0xffffffffu, s.y, k, 16);
            edge_fma4(accLo, accHi, xb, coff, vb);
        }
        s = snext;
    }
    // remainder: 4-step granularity. s already holds slots [base+sub]
    // (prefetched); slots >= cnt are zero -> phantom steps are exact no-ops.
    int rem = mcnt - base;   // 0..15
    for (int k0 = 0; k0 < rem; k0 += 4) {
        #pragma unroll
        for (int k = 0; k < 4; k++) {
            int kk = k0 + k;
            int coff = __shfl_sync(0xffffffffu, s.x, kk, 16);
            int vb   = __shfl_sync(0xffffffffu, s.y, kk, 16);
            edge_fma4(accLo, accHi, xb, coff, vb);
        }
    }

    float a0 = __uint_as_float((unsigned)accLo);
    float a1 = __uint_as_float((unsigned)(accLo >> 32));
    float a2 = __uint_as_float((unsigned)accHi);
    float a3 = __uint_as_float((unsigned)(accHi >> 32));

    int off = row * 16 + sub;   // float4 / bf16x4 granularity
    if (MODE == 2) {
        float4 a = ((const float4*)g_acc)[off];
        out2[off] = make_float4((a.x + a0) * 0.25f, (a.y + a1) * 0.25f,
                                (a.z + a2) * 0.25f, (a.w + a3) * 0.25f);
        if (sub == 0) g_cnt[row] = 0;   // restore invariant for next call
    } else {
        __nv_bfloat162* xn = (__nv_bfloat162*)((MODE == 0) ? g_xB : g_xA);
        xn[2 * off]     = __floats2bfloat162_rn(a0, a1);
        xn[2 * off + 1] = __floats2bfloat162_rn(a2, a3);
        float4 a = ((float4*)g_acc)[off];
        ((float4*)g_acc)[off] =
            make_float4(a.x + a0, a.y + a1, a.z + a2, a.w + a3);
    }
}

extern "C" void kernel_launch(void* const* d_in, const int* in_sizes, int n_in,
                              void* d_out, int out_size) {
    const float* user_emb = (const float*)d_in[0];
    const float* item_emb = (const float*)d_in[1];
    const float* edge_val = (const float*)d_in[2];
    const int*   edge_row = (const int*)d_in[3];
    const int*   edge_col = (const int*)d_in[4];
    const int nnz = in_sizes[2];

    float* out  = (float*)d_out;
    float* out2 = out + TOTAL_F;

    const int init_blocks  = (TOTAL_V4 + TPB - 1) / TPB;
    const int edge_threads = (nnz + 3) / 4;
    const int build_blocks = (edge_threads + TPB - 1) / TPB;
    const int rows_per_blk = WARPS_PB * 2;
    const int spmm_blocks  = (N_NODES + rows_per_blk - 1) / rows_per_blk;

    init_build_kernel<<<init_blocks + build_blocks, TPB>>>(
        (const float4*)user_emb, (const float4*)item_emb, (float4*)out,
        edge_row, edge_col, edge_val, nnz, init_blocks);

    spmm_ell_kernel<0><<<spmm_blocks, TPB>>>(nullptr);        // xA -> xB, acc+=
    spmm_ell_kernel<1><<<spmm_blocks, TPB>>>(nullptr);        // xB -> xA, acc+=
    spmm_ell_kernel<2><<<spmm_blocks, TPB>>>((float4*)out2);  // out2=(acc+y)/4
}

// round 13
// speedup vs baseline: 1.1750x; 1.1058x over previous
#include <cuda_runtime.h>
#include <cuda_bf16.h>

// LightGCN 3-layer. Padded-ELL (int2 slots {col*128, vbits}) built once,
// then 3x SpMM with TWO ROWS PER WARP (4 dims/lane, bf16x4 LDG.64,
// width-16 immediate-source shfl; 4-step remainder granularity).
// Round 13: the fp32 running accumulator is GONE. After layer 2, g_xB
// still holds bf16(y1) and g_xA holds bf16(y2); emb0 is fp32 in out[0:F].
// Mode 2 computes out2 = (emb0 + y1 + y2 + y3) * 0.25 directly, removing
// the acc read-modify-write from both mode-0/1 epilogues and the acc init.
// No atomics in the SpMM hot path; g_cnt self-resets in MODE 2.
// out = [emb0 (N*D fp32) | (emb0+y1+y2+y3)/4 fp32]

#define U_ROWS 100000
#define I_ROWS 50000
#define N_NODES (U_ROWS + I_ROWS)
#define EMB_D 64
#define TOTAL_F (N_NODES * EMB_D)
#define TOTAL_V4 (TOTAL_F / 4)
#define PAD 128
#define TPB 512
#define WARPS_PB (TPB / 32)

__device__ __nv_bfloat16 g_xA[TOTAL_F];
__device__ __nv_bfloat16 g_xB[TOTAL_F];
__device__ int2          g_slots[(size_t)N_NODES * PAD];  // {col*128, vbits}
__device__ int           g_cnt[N_NODES];                  // zero-init; self-reset

// ---------------------------------------------------------------------------
// build helper: one edge -> its row's next ELL slot
// ---------------------------------------------------------------------------
__device__ __forceinline__ void put_edge(int r, int c, float v) {
    int pos = atomicAdd(&g_cnt[r], 1);
    if (pos < PAD)   // always true for this dataset (Poisson(32) degrees)
        g_slots[(size_t)r * PAD + pos] = make_int2(c * 128, __float_as_int(v));
}

// ---------------------------------------------------------------------------
// fused init + build (build: 4 edges per thread, vectorized loads)
// ---------------------------------------------------------------------------
__global__ __launch_bounds__(TPB) void init_build_kernel(
        const float4* __restrict__ u,
        const float4* __restrict__ it,
        float4* __restrict__ out,
        const int*   __restrict__ rows,
        const int*   __restrict__ cols,
        const float* __restrict__ vals,
        int nnz, int init_blocks) {
    if ((int)blockIdx.x < init_blocks) {
        int i = blockIdx.x * TPB + threadIdx.x;
        if (i >= TOTAL_V4) return;
        const int u_v4 = U_ROWS * EMB_D / 4;
        float4 v = (i < u_v4) ? u[i] : it[i - u_v4];
        out[i] = v;
        __nv_bfloat162* xa = (__nv_bfloat162*)g_xA;
        xa[2 * i]     = __floats2bfloat162_rn(v.x, v.y);
        xa[2 * i + 1] = __floats2bfloat162_rn(v.z, v.w);
    } else {
        int t = (blockIdx.x - init_blocks) * TPB + threadIdx.x;
        int e = t * 4;
        if (e + 3 < nnz) {
            int4   r4 = ((const int4*)rows)[t];
            int4   c4 = ((const int4*)cols)[t];
            float4 v4 = ((const float4*)vals)[t];
            put_edge(r4.x, c4.x, v4.x);
            put_edge(r4.y, c4.y, v4.y);
            put_edge(r4.z, c4.z, v4.z);
            put_edge(r4.w, c4.w, v4.w);
        } else {
            for (; e < nnz; e++) put_edge(rows[e], cols[e], vals[e]);
        }
    }
}

// ---------------------------------------------------------------------------
// per-edge op: gather bf16x4 (4 dims), unpack 2x, two packed f32x2 FMAs
// ---------------------------------------------------------------------------
__device__ __forceinline__ void edge_fma4(unsigned long long& accLo,
                                          unsigned long long& accHi,
                                          const char* __restrict__ xb,
                                          int coff, int vbits) {
    uint2 xr = *(const uint2*)(xb + coff);   // LDG.64: 4 bf16 dims
    asm("{\n\t"
        ".reg .b32 lo, hi;\n\t"
        ".reg .b64 xx, vv;\n\t"
        "mov.b64 vv, {%3, %3};\n\t"
        "shl.b32 lo, %2, 16;\n\t"
        "and.b32 hi, %2, 0xffff0000;\n\t"
        "mov.b64 xx, {lo, hi};\n\t"
        "fma.rn.f32x2 %0, vv, xx, %0;\n\t"
        "shl.b32 lo, %4, 16;\n\t"
        "and.b32 hi, %4, 0xffff0000;\n\t"
        "mov.b64 xx, {lo, hi};\n\t"
        "fma.rn.f32x2 %1, vv, xx, %1;\n\t"
        "}"
        : "+l"(accLo), "+l"(accHi)
        : "r"(xr.x), "r"(vbits), "r"(xr.y));
}

__device__ __forceinline__ float2 bf2_to_f2(unsigned b) {
    float lo = __uint_as_float(b << 16);
    float hi = __uint_as_float(b & 0xffff0000u);
    return make_float2(lo, hi);
}

// ---------------------------------------------------------------------------
// spmm<MODE>: two rows per warp, 4 dims per lane.
//   MODE 0: x=g_xA, y1(bf16)->g_xB
//   MODE 1: x=g_xB, y2(bf16)->g_xA
//   MODE 2: x=g_xA, out2[r] = (emb0[r] + y1[r] + y2[r] + y3) * 0.25;
//           reset g_cnt[r]
// ---------------------------------------------------------------------------
template <int MODE>
__global__ __launch_bounds__(TPB, 4) void spmm_ell_kernel(
        const float4* __restrict__ emb0,   // MODE 2 only (= out[0:F])
        float4* __restrict__ out2) {
    int gw   = (blockIdx.x * blockDim.x + threadIdx.x) >> 5;
    int lane = threadIdx.x & 31;
    int half = lane >> 4;
    int sub  = lane & 15;
    int row  = gw * 2 + half;
    if (row >= N_NODES) return;

    const char* __restrict__ xb =
        (const char*)((MODE == 1) ? g_xB : g_xA) + sub * 8;

    int cnt = min(g_cnt[row], PAD);
    int mcnt = max(cnt, __shfl_xor_sync(0xffffffffu, cnt, 16));
    const int2* __restrict__ sl = g_slots + (size_t)row * PAD;

    unsigned long long accLo = 0ull;   // f32 pair: dims 4sub+0, 4sub+1
    unsigned long long accHi = 0ull;   // f32 pair: dims 4sub+2, 4sub+3

    // main loop: full 16-step chunks with next-chunk prefetch
    int2 s = sl[sub];
    int base = 0;
    for (; base + 16 <= mcnt; base += 16) {
        int nb = base + 16;
        int2 snext = (nb < mcnt) ? sl[nb + sub] : make_int2(0, 0);
        #pragma unroll
        for (int k = 0; k < 16; k++) {
            int coff = __shfl_sync(0xffffffffu, s.x, k, 16);
            int vb   = __shfl_sync(0xffffffffu, s.y, k, 16);
            edge_fma4(accLo, accHi, xb, coff, vb);
        }
        s = snext;
    }
    // remainder: 4-step granularity; slots >= cnt are zero -> exact no-ops
    int rem = mcnt - base;   // 0..15
    for (int k0 = 0; k0 < rem; k0 += 4) {
        #pragma unroll
        for (int k = 0; k < 4; k++) {
            int kk = k0 + k;
            int coff = __shfl_sync(0xffffffffu, s.x, kk, 16);
            int vb   = __shfl_sync(0xffffffffu, s.y, kk, 16);
            edge_fma4(accLo, accHi, xb, coff, vb);
        }
    }

    float a0 = __uint_as_float((unsigned)accLo);
    float a1 = __uint_as_float((unsigned)(accLo >> 32));
    float a2 = __uint_as_float((unsigned)accHi);
    float a3 = __uint_as_float((unsigned)(accHi >> 32));

    int off = row * 16 + sub;   // float4 / bf16x4 granularity
    if (MODE == 2) {
        float4 e = emb0[off];                               // fp32 emb0
        uint2 y1b = ((const uint2*)g_xB)[off];              // bf16x4 y1
        uint2 y2b = ((const uint2*)g_xA)[off];              // bf16x4 y2
        float2 y1lo = bf2_to_f2(y1b.x), y1hi = bf2_to_f2(y1b.y);
        float2 y2lo = bf2_to_f2(y2b.x), y2hi = bf2_to_f2(y2b.y);
        out2[off] = make_float4(
            (e.x + y1lo.x + y2lo.x + a0) * 0.25f,
            (e.y + y1lo.y + y2lo.y + a1) * 0.25f,
            (e.z + y1hi.x + y2hi.x + a2) * 0.25f,
            (e.w + y1hi.y + y2hi.y + a3) * 0.25f);
        if (sub == 0) g_cnt[row] = 0;   // restore invariant for next call
    } else {
        __nv_bfloat162* xn = (__nv_bfloat162*)((MODE == 0) ? g_xB : g_xA);
        xn[2 * off]     = __floats2bfloat162_rn(a0, a1);
        xn[2 * off + 1] = __floats2bfloat162_rn(a2, a3);
    }
}

extern "C" void kernel_launch(void* const* d_in, const int* in_sizes, int n_in,
                              void* d_out, int out_size) {
    const float* user_emb = (const float*)d_in[0];
    const float* item_emb = (const float*)d_in[1];
    const float* edge_val = (const float*)d_in[2];
    const int*   edge_row = (const int*)d_in[3];
    const int*   edge_col = (const int*)d_in[4];
    const int nnz = in_sizes[2];

    float* out  = (float*)d_out;
    float* out2 = out + TOTAL_F;

    const int init_blocks  = (TOTAL_V4 + TPB - 1) / TPB;
    const int edge_threads = (nnz + 3) / 4;
    const int build_blocks = (edge_threads + TPB - 1) / TPB;
    const int rows_per_blk = WARPS_PB * 2;
    const int spmm_blocks  = (N_NODES + rows_per_blk - 1) / rows_per_blk;

    init_build_kernel<<<init_blocks + build_blocks, TPB>>>(
        (const float4*)user_emb, (const float4*)item_emb, (float4*)out,
        edge_row, edge_col, edge_val, nnz, init_blocks);

    spmm_ell_kernel<0><<<spmm_blocks, TPB>>>(nullptr, nullptr); // xA -> xB (y1)
    spmm_ell_kernel<1><<<spmm_blocks, TPB>>>(nullptr, nullptr); // xB -> xA (y2)
    spmm_ell_kernel<2><<<spmm_blocks, TPB>>>((const float4*)out,
                                             (float4*)out2);    // final blend
}